// round 1
// baseline (speedup 1.0000x reference)
#include <cuda_runtime.h>
#include <cuda_bf16.h>
#include <float.h>

// Problem constants
#define BATCH 4
#define SLEN  32768
#define C1    128
#define L1V   16384
#define C2    256
#define L2V   8192
#define HID   512
#define L3V   4096
#define VOCAB 2048
#define KCB   4

// Scratch (module-static device memory; no runtime allocation)
__device__ float g_y1[BATCH * C1 * L1V];
__device__ float g_y2[BATCH * C2 * L2V];
__device__ float g_y3[BATCH * HID * L3V];   // feats, channel-major [b][h][l]
__device__ float g_c2[KCB * VOCAB];
__device__ int   g_tok[BATCH * KCB * L3V];

// ---------------------------------------------------------------------------
// conv1: [B,1,S] -> [B,128,16384], relu. One thread per output element.
// ---------------------------------------------------------------------------
__global__ void conv1_k(const float* __restrict__ a,
                        const float* __restrict__ w,
                        const float* __restrict__ bias) {
    int idx = blockIdx.x * blockDim.x + threadIdx.x;   // < 2^23
    int l = idx & (L1V - 1);
    int c = (idx >> 14) & (C1 - 1);
    int b = idx >> 21;
    const float* ab = a + (size_t)b * SLEN;
    int p0 = 2 * l - 3;
    float acc = bias[c];
#pragma unroll
    for (int t = 0; t < 7; t++) {
        int p = p0 + t;
        float xv = (p >= 0 && p < SLEN) ? __ldg(&ab[p]) : 0.f;
        acc = fmaf(__ldg(&w[c * 7 + t]), xv, acc);
    }
    g_y1[idx] = fmaxf(acc, 0.f);
}

// ---------------------------------------------------------------------------
// conv2/conv3: implicit GEMM. Block tile 64co x 64l, thread tile 4x4.
// Weights staged as ws[ci][t][co] (float4 loads), x as sliding register window.
// S3 = false: g_y1 -> g_y2 (relu).  S3 = true: g_y2 -> g_y3 (no relu).
// ---------------------------------------------------------------------------
template<int CI, int LIN, int CO, bool RELU, bool S3>
__global__ __launch_bounds__(256) void conv_k(const float* __restrict__ w,
                                              const float* __restrict__ bias) {
    constexpr int LOUT = LIN / 2;
    constexpr int CK = 8;
    __shared__ float xs[CK][136];
    __shared__ float ws[CK][7][68];

    const float* x = S3 ? g_y2 : g_y1;
    float* y       = S3 ? g_y3 : g_y2;

    int tid = threadIdx.x;
    int tx = tid & 15;        // l-group (4 contiguous l)
    int ty = tid >> 4;        // co-group (4 contiguous co)
    int l0 = blockIdx.x * 64;
    int co0 = blockIdx.y * 64;
    int b = blockIdx.z;
    const float* xb = x + (size_t)b * CI * LIN;
    int base = 2 * l0 - 3;

    float acc[4][4];
#pragma unroll
    for (int j = 0; j < 4; j++)
#pragma unroll
        for (int i = 0; i < 4; i++) acc[j][i] = 0.f;

    for (int ci0 = 0; ci0 < CI; ci0 += CK) {
        __syncthreads();
        // stage x window: positions [base, base+133]
        for (int i = tid; i < CK * 134; i += 256) {
            int ci = i / 134;
            int p = i - ci * 134;
            int gp = base + p;
            float v = (gp >= 0 && gp < LIN) ? xb[(size_t)(ci0 + ci) * LIN + gp] : 0.f;
            xs[ci][p] = v;
        }
        // stage weights: contiguous 56 floats per co in global
        for (int i = tid; i < 64 * 56; i += 256) {
            int co = i / 56;
            int r = i - co * 56;
            int ci = r / 7;
            int t = r - ci * 7;
            ws[ci][t][co] = w[((size_t)(co0 + co) * CI + ci0 + ci) * 7 + t];
        }
        __syncthreads();

#pragma unroll
        for (int ci = 0; ci < CK; ci++) {
            float xr[13];
            float4 xa = *(const float4*)&xs[ci][8 * tx];
            float4 xb4 = *(const float4*)&xs[ci][8 * tx + 4];
            float4 xc = *(const float4*)&xs[ci][8 * tx + 8];
            xr[0] = xa.x;  xr[1] = xa.y;  xr[2] = xa.z;  xr[3] = xa.w;
            xr[4] = xb4.x; xr[5] = xb4.y; xr[6] = xb4.z; xr[7] = xb4.w;
            xr[8] = xc.x;  xr[9] = xc.y;  xr[10] = xc.z; xr[11] = xc.w;
            xr[12] = xs[ci][8 * tx + 12];
#pragma unroll
            for (int t = 0; t < 7; t++) {
                float4 w4 = *(const float4*)&ws[ci][t][ty * 4];
#pragma unroll
                for (int i = 0; i < 4; i++) {
                    float xv = xr[2 * i + t];
                    acc[0][i] = fmaf(w4.x, xv, acc[0][i]);
                    acc[1][i] = fmaf(w4.y, xv, acc[1][i]);
                    acc[2][i] = fmaf(w4.z, xv, acc[2][i]);
                    acc[3][i] = fmaf(w4.w, xv, acc[3][i]);
                }
            }
        }
    }
    // epilogue
#pragma unroll
    for (int j = 0; j < 4; j++) {
        int co = co0 + ty * 4 + j;
        float bv = bias[co];
#pragma unroll
        for (int i = 0; i < 4; i++) {
            float v = acc[j][i] + bv;
            if (RELU) v = fmaxf(v, 0.f);
            y[((size_t)b * CO + co) * LOUT + l0 + tx * 4 + i] = v;
        }
    }
}

// ---------------------------------------------------------------------------
// c2[k][v] = ||codebook[k][v]||^2 : one warp per row
// ---------------------------------------------------------------------------
__global__ void c2_k(const float* __restrict__ cb) {
    int row = blockIdx.x * 8 + (threadIdx.x >> 5);
    int lane = threadIdx.x & 31;
    const float* r = cb + (size_t)row * HID;
    float s = 0.f;
    for (int h = lane * 4; h < HID; h += 128) {
        float4 v = *(const float4*)&r[h];
        s = fmaf(v.x, v.x, s); s = fmaf(v.y, v.y, s);
        s = fmaf(v.z, v.z, s); s = fmaf(v.w, v.w, s);
    }
#pragma unroll
    for (int o = 16; o; o >>= 1) s += __shfl_xor_sync(0xFFFFFFFFu, s, o);
    if (!lane) g_c2[row] = s;
}

// ---------------------------------------------------------------------------
// dist: fused cross-GEMM + argmin.
// Grid (L3/128, KCB, BATCH), block 256. Tile 128l x 128v, 8x8 per thread.
// argmin_v ( c2[v] - 2 * f.c_v )   (f^2 term is constant per l -> dropped)
// ---------------------------------------------------------------------------
__global__ __launch_bounds__(256) void dist_k(const float* __restrict__ cb,
                                              float* __restrict__ out_tok) {
    __shared__ float fs[16][132];
    __shared__ float cs[16][132];
    __shared__ float c2s[128];
    __shared__ float sbv[128][17];
    __shared__ int   sbi[128][17];

    int tid = threadIdx.x;
    int tx = tid & 15;        // v: 8 contiguous = tx*8..tx*8+7
    int ty = tid >> 4;        // l: 8 contiguous = ty*8..ty*8+7
    int l0 = blockIdx.x * 128;
    int k = blockIdx.y;
    int b = blockIdx.z;

    const float* f = g_y3 + (size_t)b * HID * L3V;       // [h][l]
    const float* cbk = cb + (size_t)k * VOCAB * HID;     // [v][h]

    float best[8];
    int bidx[8];
#pragma unroll
    for (int i = 0; i < 8; i++) { best[i] = FLT_MAX; bidx[i] = 0; }

    for (int v0 = 0; v0 < VOCAB; v0 += 128) {
        __syncthreads();
        if (tid < 128) c2s[tid] = g_c2[k * VOCAB + v0 + tid];

        float acc[8][8];
#pragma unroll
        for (int i = 0; i < 8; i++)
#pragma unroll
            for (int j = 0; j < 8; j++) acc[i][j] = 0.f;

        for (int ht = 0; ht < HID; ht += 16) {
            // fs[hh][l] <- feats (coalesced rows)
            for (int i = tid; i < 512; i += 256) {
                int hh = i >> 5;
                int c = i & 31;
                *(float4*)&fs[hh][c * 4] =
                    *(const float4*)&f[(size_t)(ht + hh) * L3V + l0 + c * 4];
            }
            // cs[hh][v] <- codebook transposed (groups of 4 tids per row)
            for (int i = tid; i < 512; i += 256) {
                int vv = i >> 2;
                int c = i & 3;
                float4 t4 = *(const float4*)&cbk[(size_t)(v0 + vv) * HID + ht + c * 4];
                cs[c * 4 + 0][vv] = t4.x;
                cs[c * 4 + 1][vv] = t4.y;
                cs[c * 4 + 2][vv] = t4.z;
                cs[c * 4 + 3][vv] = t4.w;
            }
            __syncthreads();
#pragma unroll
            for (int hh = 0; hh < 16; hh++) {
                float4 f0 = *(const float4*)&fs[hh][ty * 8];
                float4 f1 = *(const float4*)&fs[hh][ty * 8 + 4];
                float4 c0 = *(const float4*)&cs[hh][tx * 8];
                float4 c1 = *(const float4*)&cs[hh][tx * 8 + 4];
                float fr[8] = {f0.x, f0.y, f0.z, f0.w, f1.x, f1.y, f1.z, f1.w};
                float cr[8] = {c0.x, c0.y, c0.z, c0.w, c1.x, c1.y, c1.z, c1.w};
#pragma unroll
                for (int i = 0; i < 8; i++)
#pragma unroll
                    for (int j = 0; j < 8; j++)
                        acc[i][j] = fmaf(fr[i], cr[j], acc[i][j]);
            }
            __syncthreads();
        }
        // argmin update (v ascending within thread -> strict < keeps first)
#pragma unroll
        for (int i = 0; i < 8; i++) {
#pragma unroll
            for (int j = 0; j < 8; j++) {
                int vloc = tx * 8 + j;
                float d = fmaf(-2.f, acc[i][j], c2s[vloc]);
                if (d < best[i]) { best[i] = d; bidx[i] = v0 + vloc; }
            }
        }
    }

    // cross-thread reduction per l (tie -> smaller index, matching jnp.argmin)
#pragma unroll
    for (int i = 0; i < 8; i++) {
        sbv[ty * 8 + i][tx] = best[i];
        sbi[ty * 8 + i][tx] = bidx[i];
    }
    __syncthreads();
    if (tid < 128) {
        int l = tid;
        float bv = sbv[l][0];
        int bi = sbi[l][0];
#pragma unroll
        for (int t = 1; t < 16; t++) {
            float v = sbv[l][t];
            int ix = sbi[l][t];
            if (v < bv || (v == bv && ix < bi)) { bv = v; bi = ix; }
        }
        size_t o = ((size_t)b * KCB + k) * L3V + l0 + l;
        out_tok[o] = (float)bi;
        g_tok[o] = bi;
    }
}

// ---------------------------------------------------------------------------
// emb: out[b][l][h] = mean_k embedding[tok[b][k][l]][h]
// ---------------------------------------------------------------------------
__global__ void emb_k(const float* __restrict__ E, float* __restrict__ out) {
    int pos = blockIdx.x;            // b*L3V + l
    int b = pos >> 12;
    int l = pos & (L3V - 1);
    int t0 = g_tok[((size_t)b * KCB + 0) * L3V + l];
    int t1 = g_tok[((size_t)b * KCB + 1) * L3V + l];
    int t2 = g_tok[((size_t)b * KCB + 2) * L3V + l];
    int t3 = g_tok[((size_t)b * KCB + 3) * L3V + l];
    int h = threadIdx.x;             // float4 index, 128 threads
    float4 a = ((const float4*)(E + (size_t)t0 * HID))[h];
    float4 b4 = ((const float4*)(E + (size_t)t1 * HID))[h];
    float4 c = ((const float4*)(E + (size_t)t2 * HID))[h];
    float4 d = ((const float4*)(E + (size_t)t3 * HID))[h];
    float4 r;
    r.x = 0.25f * (a.x + b4.x + c.x + d.x);
    r.y = 0.25f * (a.y + b4.y + c.y + d.y);
    r.z = 0.25f * (a.z + b4.z + c.z + d.z);
    r.w = 0.25f * (a.w + b4.w + c.w + d.w);
    ((float4*)(out + (size_t)pos * HID))[h] = r;
}

// ---------------------------------------------------------------------------
extern "C" void kernel_launch(void* const* d_in, const int* in_sizes, int n_in,
                              void* d_out, int out_size) {
    const float* audio     = (const float*)d_in[0];
    const float* w1        = (const float*)d_in[1];
    const float* b1        = (const float*)d_in[2];
    const float* w2        = (const float*)d_in[3];
    const float* b2        = (const float*)d_in[4];
    const float* w3        = (const float*)d_in[5];
    const float* b3        = (const float*)d_in[6];
    const float* codebook  = (const float*)d_in[7];
    const float* embedding = (const float*)d_in[8];

    float* out_tok = (float*)d_out;                                  // [B,K,L3]
    float* out_emb = out_tok + (size_t)BATCH * KCB * L3V;            // [B,L3,H]

    conv1_k<<<(BATCH * C1 * L1V) / 256, 256>>>(audio, w1, b1);
    conv_k<C1, L1V, C2, true,  false><<<dim3(L2V / 64, C2 / 64, BATCH), 256>>>(w2, b2);
    conv_k<C2, L2V, HID, false, true ><<<dim3(L3V / 64, HID / 64, BATCH), 256>>>(w3, b3);
    c2_k<<<(KCB * VOCAB) / 8, 256>>>(codebook);
    dist_k<<<dim3(L3V / 128, KCB, BATCH), 256>>>(codebook, out_tok);
    emb_k<<<BATCH * L3V, 128>>>(embedding, out_emb);
}

// round 2
// speedup vs baseline: 1.0707x; 1.0707x over previous
#include <cuda_runtime.h>
#include <cuda_bf16.h>
#include <float.h>

// Problem constants
#define BATCH 4
#define SLEN  32768
#define C1    128
#define L1V   16384
#define C2    256
#define L2V   8192
#define HID   512
#define L3V   4096
#define VOCAB 2048
#define KCB   4

typedef unsigned long long u64;

// Packed dual-fp32 FMA (Blackwell FFMA.F32x2). Bit-exact IEEE fp32 per lane.
__device__ __forceinline__ u64 ffma2(u64 a, u64 b, u64 c) {
    u64 d;
    asm("fma.rn.f32x2 %0, %1, %2, %3;" : "=l"(d) : "l"(a), "l"(b), "l"(c));
    return d;
}
__device__ __forceinline__ u64 pack2(float x, float y) {
    u64 d;
    asm("mov.b64 %0, {%1, %2};" : "=l"(d) : "f"(x), "f"(y));
    return d;
}
__device__ __forceinline__ float2 unpack2(u64 d) {
    float2 r;
    asm("mov.b64 {%0, %1}, %2;" : "=f"(r.x), "=f"(r.y) : "l"(d));
    return r;
}

// Scratch (module-static device memory; no runtime allocation)
__device__ float g_y1[BATCH * C1 * L1V];
__device__ float g_y2[BATCH * C2 * L2V];
__device__ float g_y3[BATCH * HID * L3V];   // feats, channel-major [b][h][l]
__device__ float g_c2[KCB * VOCAB];
__device__ int   g_tok[BATCH * KCB * L3V];

// ---------------------------------------------------------------------------
// conv1: [B,1,S] -> [B,128,16384], relu. One thread per output element.
// ---------------------------------------------------------------------------
__global__ void conv1_k(const float* __restrict__ a,
                        const float* __restrict__ w,
                        const float* __restrict__ bias) {
    int idx = blockIdx.x * blockDim.x + threadIdx.x;
    int l = idx & (L1V - 1);
    int c = (idx >> 14) & (C1 - 1);
    int b = idx >> 21;
    const float* ab = a + (size_t)b * SLEN;
    int p0 = 2 * l - 3;
    float acc = bias[c];
#pragma unroll
    for (int t = 0; t < 7; t++) {
        int p = p0 + t;
        float xv = (p >= 0 && p < SLEN) ? __ldg(&ab[p]) : 0.f;
        acc = fmaf(__ldg(&w[c * 7 + t]), xv, acc);
    }
    g_y1[idx] = fmaxf(acc, 0.f);
}

// ---------------------------------------------------------------------------
// conv2/conv3: implicit GEMM, f32x2 packed FMA over the co dimension.
// Block tile 64co x 64l, thread tile 4co x 4l (2 packed co-pairs x 4 l).
// ---------------------------------------------------------------------------
template<int CI, int LIN, int CO, bool RELU, bool S3>
__global__ __launch_bounds__(256) void conv_k(const float* __restrict__ w,
                                              const float* __restrict__ bias) {
    constexpr int LOUT = LIN / 2;
    constexpr int CK = 8;
    __shared__ __align__(16) float xs[CK][136];
    __shared__ __align__(16) float ws[CK][7][68];

    const float* x = S3 ? g_y2 : g_y1;
    float* y       = S3 ? g_y3 : g_y2;

    int tid = threadIdx.x;
    int tx = tid & 15;        // l-group (4 contiguous l)
    int ty = tid >> 4;        // co-group (4 contiguous co)
    int l0 = blockIdx.x * 64;
    int co0 = blockIdx.y * 64;
    int b = blockIdx.z;
    const float* xb = x + (size_t)b * CI * LIN;
    int base = 2 * l0 - 3;

    u64 accA[4], accB[4];     // accA: co pair (ty*4+0, +1); accB: (+2, +3)
#pragma unroll
    for (int i = 0; i < 4; i++) { accA[i] = 0ull; accB[i] = 0ull; }

    for (int ci0 = 0; ci0 < CI; ci0 += CK) {
        __syncthreads();
        // stage x window: positions [base, base+133]
        for (int i = tid; i < CK * 134; i += 256) {
            int ci = i / 134;
            int p = i - ci * 134;
            int gp = base + p;
            float v = (gp >= 0 && gp < LIN) ? xb[(size_t)(ci0 + ci) * LIN + gp] : 0.f;
            xs[ci][p] = v;
        }
        // stage weights: ws[ci][t][co]
        for (int i = tid; i < 64 * 56; i += 256) {
            int co = i / 56;
            int r = i - co * 56;
            int ci = r / 7;
            int t = r - ci * 7;
            ws[ci][t][co] = w[((size_t)(co0 + co) * CI + ci0 + ci) * 7 + t];
        }
        __syncthreads();

#pragma unroll
        for (int ci = 0; ci < CK; ci++) {
            float xr[13];
            float4 xa = *(const float4*)&xs[ci][8 * tx];
            float4 xb4 = *(const float4*)&xs[ci][8 * tx + 4];
            float4 xc = *(const float4*)&xs[ci][8 * tx + 8];
            xr[0] = xa.x;  xr[1] = xa.y;  xr[2] = xa.z;  xr[3] = xa.w;
            xr[4] = xb4.x; xr[5] = xb4.y; xr[6] = xb4.z; xr[7] = xb4.w;
            xr[8] = xc.x;  xr[9] = xc.y;  xr[10] = xc.z; xr[11] = xc.w;
            xr[12] = xs[ci][8 * tx + 12];
            u64 xd[13];
#pragma unroll
            for (int p = 0; p < 13; p++) xd[p] = pack2(xr[p], xr[p]);
#pragma unroll
            for (int t = 0; t < 7; t++) {
                const u64* wp = (const u64*)&ws[ci][t][ty * 4];
                u64 w01 = wp[0];
                u64 w23 = wp[1];
#pragma unroll
                for (int i = 0; i < 4; i++) {
                    u64 xv = xd[2 * i + t];
                    accA[i] = ffma2(w01, xv, accA[i]);
                    accB[i] = ffma2(w23, xv, accB[i]);
                }
            }
        }
    }
    // epilogue
    float bv0 = bias[co0 + ty * 4 + 0];
    float bv1 = bias[co0 + ty * 4 + 1];
    float bv2 = bias[co0 + ty * 4 + 2];
    float bv3 = bias[co0 + ty * 4 + 3];
#pragma unroll
    for (int i = 0; i < 4; i++) {
        float2 a2 = unpack2(accA[i]);
        float2 b2 = unpack2(accB[i]);
        float v0 = a2.x + bv0, v1 = a2.y + bv1, v2 = b2.x + bv2, v3 = b2.y + bv3;
        if (RELU) {
            v0 = fmaxf(v0, 0.f); v1 = fmaxf(v1, 0.f);
            v2 = fmaxf(v2, 0.f); v3 = fmaxf(v3, 0.f);
        }
        int lo = l0 + tx * 4 + i;
        y[((size_t)b * CO + co0 + ty * 4 + 0) * LOUT + lo] = v0;
        y[((size_t)b * CO + co0 + ty * 4 + 1) * LOUT + lo] = v1;
        y[((size_t)b * CO + co0 + ty * 4 + 2) * LOUT + lo] = v2;
        y[((size_t)b * CO + co0 + ty * 4 + 3) * LOUT + lo] = v3;
    }
}

// ---------------------------------------------------------------------------
// c2[k][v] = ||codebook[k][v]||^2 : one warp per row
// ---------------------------------------------------------------------------
__global__ void c2_k(const float* __restrict__ cb) {
    int row = blockIdx.x * 8 + (threadIdx.x >> 5);
    int lane = threadIdx.x & 31;
    const float* r = cb + (size_t)row * HID;
    float s = 0.f;
    for (int h = lane * 4; h < HID; h += 128) {
        float4 v = *(const float4*)&r[h];
        s = fmaf(v.x, v.x, s); s = fmaf(v.y, v.y, s);
        s = fmaf(v.z, v.z, s); s = fmaf(v.w, v.w, s);
    }
#pragma unroll
    for (int o = 16; o; o >>= 1) s += __shfl_xor_sync(0xFFFFFFFFu, s, o);
    if (!lane) g_c2[row] = s;
}

// ---------------------------------------------------------------------------
// dist: fused cross-GEMM + argmin, f32x2 packed over the v dimension.
// Grid (L3/128, KCB, BATCH), block 256. Tile 128l x 128v, 8l x 8v per thread
// (8 x 4 packed pairs). argmin_v ( c2[v] - 2*f.c_v ).
// ---------------------------------------------------------------------------
__global__ __launch_bounds__(256) void dist_k(const float* __restrict__ cb,
                                              float* __restrict__ out_tok) {
    __shared__ __align__(16) float fs[16][132];
    __shared__ __align__(16) float cs[16][132];
    __shared__ float c2s[128];
    __shared__ float sbv[128][17];
    __shared__ int   sbi[128][17];

    int tid = threadIdx.x;
    int tx = tid & 15;        // v: 8 contiguous = tx*8..tx*8+7
    int ty = tid >> 4;        // l: 8 contiguous = ty*8..ty*8+7
    int l0 = blockIdx.x * 128;
    int k = blockIdx.y;
    int b = blockIdx.z;

    const float* f = g_y3 + (size_t)b * HID * L3V;       // [h][l]
    const float* cbk = cb + (size_t)k * VOCAB * HID;     // [v][h]

    float best[8];
    int bidx[8];
#pragma unroll
    for (int i = 0; i < 8; i++) { best[i] = FLT_MAX; bidx[i] = 0; }

    for (int v0 = 0; v0 < VOCAB; v0 += 128) {
        __syncthreads();
        if (tid < 128) c2s[tid] = g_c2[k * VOCAB + v0 + tid];

        u64 acc[8][4];        // [l][v-pair]
#pragma unroll
        for (int i = 0; i < 8; i++)
#pragma unroll
            for (int j = 0; j < 4; j++) acc[i][j] = 0ull;

        for (int ht = 0; ht < HID; ht += 16) {
            // fs[hh][l] <- feats (coalesced rows)
            for (int i = tid; i < 512; i += 256) {
                int hh = i >> 5;
                int c = i & 31;
                *(float4*)&fs[hh][c * 4] =
                    *(const float4*)&f[(size_t)(ht + hh) * L3V + l0 + c * 4];
            }
            // cs[hh][v] <- codebook transposed
            for (int i = tid; i < 512; i += 256) {
                int vv = i >> 2;
                int c = i & 3;
                float4 t4 = *(const float4*)&cbk[(size_t)(v0 + vv) * HID + ht + c * 4];
                cs[c * 4 + 0][vv] = t4.x;
                cs[c * 4 + 1][vv] = t4.y;
                cs[c * 4 + 2][vv] = t4.z;
                cs[c * 4 + 3][vv] = t4.w;
            }
            __syncthreads();
#pragma unroll
            for (int hh = 0; hh < 16; hh++) {
                float4 f0 = *(const float4*)&fs[hh][ty * 8];
                float4 f1 = *(const float4*)&fs[hh][ty * 8 + 4];
                float fr[8] = {f0.x, f0.y, f0.z, f0.w, f1.x, f1.y, f1.z, f1.w};
                const u64* cp = (const u64*)&cs[hh][tx * 8];
                u64 c0 = cp[0], c1 = cp[1], c2p = cp[2], c3 = cp[3];
#pragma unroll
                for (int i = 0; i < 8; i++) {
                    u64 fb = pack2(fr[i], fr[i]);
                    acc[i][0] = ffma2(fb, c0, acc[i][0]);
                    acc[i][1] = ffma2(fb, c1, acc[i][1]);
                    acc[i][2] = ffma2(fb, c2p, acc[i][2]);
                    acc[i][3] = ffma2(fb, c3, acc[i][3]);
                }
            }
            __syncthreads();
        }
        // argmin update (v ascending within thread -> strict < keeps first)
#pragma unroll
        for (int i = 0; i < 8; i++) {
#pragma unroll
            for (int j = 0; j < 4; j++) {
                float2 a2 = unpack2(acc[i][j]);
                int vloc = tx * 8 + 2 * j;
                float d0 = fmaf(-2.f, a2.x, c2s[vloc]);
                if (d0 < best[i]) { best[i] = d0; bidx[i] = v0 + vloc; }
                float d1 = fmaf(-2.f, a2.y, c2s[vloc + 1]);
                if (d1 < best[i]) { best[i] = d1; bidx[i] = v0 + vloc + 1; }
            }
        }
    }

    // cross-thread reduction per l (tie -> smaller index, matching jnp.argmin)
#pragma unroll
    for (int i = 0; i < 8; i++) {
        sbv[ty * 8 + i][tx] = best[i];
        sbi[ty * 8 + i][tx] = bidx[i];
    }
    __syncthreads();
    if (tid < 128) {
        int l = tid;
        float bv = sbv[l][0];
        int bi = sbi[l][0];
#pragma unroll
        for (int t = 1; t < 16; t++) {
            float v = sbv[l][t];
            int ix = sbi[l][t];
            if (v < bv || (v == bv && ix < bi)) { bv = v; bi = ix; }
        }
        size_t o = ((size_t)b * KCB + k) * L3V + l0 + l;
        out_tok[o] = (float)bi;
        g_tok[o] = bi;
    }
}

// ---------------------------------------------------------------------------
// emb: out[b][l][h] = mean_k embedding[tok[b][k][l]][h]
// ---------------------------------------------------------------------------
__global__ void emb_k(const float* __restrict__ E, float* __restrict__ out) {
    int pos = blockIdx.x;            // b*L3V + l
    int b = pos >> 12;
    int l = pos & (L3V - 1);
    int t0 = g_tok[((size_t)b * KCB + 0) * L3V + l];
    int t1 = g_tok[((size_t)b * KCB + 1) * L3V + l];
    int t2 = g_tok[((size_t)b * KCB + 2) * L3V + l];
    int t3 = g_tok[((size_t)b * KCB + 3) * L3V + l];
    int h = threadIdx.x;
    float4 a = ((const float4*)(E + (size_t)t0 * HID))[h];
    float4 b4 = ((const float4*)(E + (size_t)t1 * HID))[h];
    float4 c = ((const float4*)(E + (size_t)t2 * HID))[h];
    float4 d = ((const float4*)(E + (size_t)t3 * HID))[h];
    float4 r;
    r.x = 0.25f * (a.x + b4.x + c.x + d.x);
    r.y = 0.25f * (a.y + b4.y + c.y + d.y);
    r.z = 0.25f * (a.z + b4.z + c.z + d.z);
    r.w = 0.25f * (a.w + b4.w + c.w + d.w);
    ((float4*)(out + (size_t)pos * HID))[h] = r;
}

// ---------------------------------------------------------------------------
extern "C" void kernel_launch(void* const* d_in, const int* in_sizes, int n_in,
                              void* d_out, int out_size) {
    const float* audio     = (const float*)d_in[0];
    const float* w1        = (const float*)d_in[1];
    const float* b1        = (const float*)d_in[2];
    const float* w2        = (const float*)d_in[3];
    const float* b2        = (const float*)d_in[4];
    const float* w3        = (const float*)d_in[5];
    const float* b3        = (const float*)d_in[6];
    const float* codebook  = (const float*)d_in[7];
    const float* embedding = (const float*)d_in[8];

    float* out_tok = (float*)d_out;                                  // [B,K,L3]
    float* out_emb = out_tok + (size_t)BATCH * KCB * L3V;            // [B,L3,H]

    conv1_k<<<(BATCH * C1 * L1V) / 256, 256>>>(audio, w1, b1);
    conv_k<C1, L1V, C2, true,  false><<<dim3(L2V / 64, C2 / 64, BATCH), 256>>>(w2, b2);
    conv_k<C2, L2V, HID, false, true ><<<dim3(L3V / 64, HID / 64, BATCH), 256>>>(w3, b3);
    c2_k<<<(KCB * VOCAB) / 8, 256>>>(codebook);
    dist_k<<<dim3(L3V / 128, KCB, BATCH), 256>>>(codebook, out_tok);
    emb_k<<<BATCH * L3V, 128>>>(embedding, out_emb);
}